// round 14
// baseline (speedup 1.0000x reference)
#include <cuda_runtime.h>

#define NN 50
#define TPB 256
#define IPB 2
#define EPSV 1e-8f
#define EMAXE 256
#define VOCAB 21128

typedef unsigned long long ull;

// Precomputed projected embedding table: row v = [emb[v]@conv_w (10) | emb[v]@cross_w (10)]
__device__ float g_ptab[VOCAB * 20];

__device__ __forceinline__ ull pk2(float a, float b) {
    union { float2 f; ull u; } c;
    c.f = make_float2(a, b);
    return c.u;
}
__device__ __forceinline__ float2 unpk(ull u) {
    union { float2 f; ull u; } c;
    c.u = u;
    return c.f;
}
__device__ __forceinline__ float unpk_sum(ull u) {
    float2 f = unpk(u);
    return f.x + f.y;
}
#define FMA2(d, a, b) asm("fma.rn.f32x2 %0, %1, %2, %0;" : "+l"(d) : "l"(a), "l"(b))

// ---------------- Precompute: g_ptab = emb_table @ [conv_w | cross_w] ----------------
// v2 (measured best): 4 threads per vocab row; thread computes 5 outputs over all 128 dims.
__global__ void __launch_bounds__(128) ptab_kernel(
    const float* __restrict__ emb,
    const float* __restrict__ conv_w,
    const float* __restrict__ cross_w)
{
    __shared__ float wt[20][132];
    const int t = threadIdx.x;
    for (int i = t; i < 20 * 128; i += 128) {
        int j = i >> 7, d = i & 127;
        wt[j][d] = (j < 10) ? conv_w[d * 10 + j] : cross_w[d * 10 + (j - 10)];
    }
    __syncthreads();
    int idx = blockIdx.x * 128 + t;
    if (idx >= VOCAB * 4) return;
    int v = idx >> 2;
    int jq = idx & 3;          // j-quarter: outputs jq*5 .. jq*5+4

    ull acc[5];
#pragma unroll
    for (int q = 0; q < 5; q++) acc[q] = 0ull;
    const float4* ep = reinterpret_cast<const float4*>(emb + (size_t)v * 128);
    const float* wbase = &wt[jq * 5][0];
#pragma unroll 4
    for (int c4 = 0; c4 < 32; c4++) {
        float4 e = ep[c4];
        ull e01 = pk2(e.x, e.y), e23 = pk2(e.z, e.w);
#pragma unroll
        for (int q = 0; q < 5; q++) {
            float4 w = *reinterpret_cast<const float4*>(wbase + q * 132 + c4 * 4);
            FMA2(acc[q], e01, pk2(w.x, w.y));
            FMA2(acc[q], e23, pk2(w.z, w.w));
        }
    }
    float* op = g_ptab + (size_t)v * 20 + jq * 5;
#pragma unroll
    for (int q = 0; q < 5; q++) op[q] = unpk_sum(acc[q]);
}

// ---------------- Main kernel: 2 items per CTA ----------------
struct PerItem {
    union {
        struct {
            float convp[2][NN][12];      // 4800 B (12-stride, 16B-aligned rows)
            float crosspp[2][25][20];    // 4000 B — PAIR-PACKED: rows 2q,2q+1 contiguous
        } cc;
        float h2[2][NN][21];             // 8400 B
    } u;
    float dinv[2][NN];
    float gmax[2][20];
    float pmax[3][2][20];
    float feat[80];
    float zz[2][40];
    int   cnt[2][52];                  // histogram, then scatter cursor
    int   start[2][52];                // exclusive prefix (start[g][NN] = E)
    unsigned short srcsorted[2][EMAXE];
};

struct Smem {
    float attn[NN][51];                // shared constants (loaded once per CTA)
    float _p0[2];
    float assign[NN][10];              // rows are 8-byte aligned (40B stride)
    float mpw1p[11][20];
    float mpw2p[20][20];
    float mpb1[20], mpb2[20], convb[12];
    PerItem it[IPB];
};

__global__ void __launch_bounds__(TPB, 4) gmn_kernel(
    const int* __restrict__ utok, const int* __restrict__ rtok,
    const int* __restrict__ uadj, const int* __restrict__ radj,
    const float* __restrict__ attn,
    const float* __restrict__ assignw, const float* __restrict__ conv_b,
    const float* __restrict__ mpw1, const float* __restrict__ mpb1,
    const float* __restrict__ mpw2, const float* __restrict__ mpb2,
    const float* __restrict__ fw1, const float* __restrict__ fb1,
    const float* __restrict__ fw2, const float* __restrict__ fb2,
    float* __restrict__ out, int E)
{
    extern __shared__ char smraw[];
    Smem& s = *reinterpret_cast<Smem*>(smraw);
    const int t = threadIdx.x;
    const int tt = t & 127;            // per-item thread id
    const int p = t >> 7;              // item slot 0/1
    const int item = blockIdx.x * IPB + p;

    // ---------------- Phase 0: shared constants (256 threads) + per-item init ----------------
    for (int i = t; i < NN * NN; i += TPB) s.attn[i / NN][i % NN] = attn[i];
    for (int i = t; i < NN * 10; i += TPB) s.assign[i / 10][i % 10] = assignw[i];
    for (int i = t; i < 11 * 20; i += TPB) s.mpw1p[i / 20][i % 20] = mpw1[i];
    for (int i = t; i < 20 * 20; i += TPB) s.mpw2p[i / 20][i % 20] = mpw2[i];
    if (t < 20) { s.mpb1[t] = mpb1[t]; s.mpb2[t] = mpb2[t]; }
    if (t < 12) s.convb[t] = (t < 10) ? conv_b[t] : 0.0f;
    if (tt < 104) reinterpret_cast<int*>(&s.it[p].cnt[0][0])[tt] = 0;
    __syncthreads();

    // ---------------- Phase 0b: histogram (gmem dst reads) + ptab gather ----------------
    for (int i = tt; i < 2 * E; i += 128) {
        int g = i / E, e = i - g * E;
        const int* adj = (g == 0 ? uadj : radj) + (size_t)item * 2 * E;
        atomicAdd(&s.it[p].cnt[g][adj[E + e]], 1);
    }
    if (tt < 100) {
        int g = tt / NN, r = tt - (tt / NN) * NN;
        int tokv = (g == 0 ? utok : rtok)[item * NN + r];
        const float4* tb = reinterpret_cast<const float4*>(g_ptab + (size_t)tokv * 20);
        float4 v0 = tb[0], v1 = tb[1], v2 = tb[2], v3 = tb[3], v4 = tb[4];
        float4* cp = reinterpret_cast<float4*>(&s.it[p].u.cc.convp[g][r][0]);
        cp[0] = v0;
        cp[1] = v1;
        cp[2] = make_float4(v2.x, v2.y, 0.f, 0.f);
        // cross projection into pair-packed layout: row r lives in pair r>>1, half r&1
        float* xb = &s.it[p].u.cc.crosspp[g][r >> 1][0];
        if ((r & 1) == 0) {
            *reinterpret_cast<float4*>(xb + 0) = make_float4(v2.z, v2.w, v3.x, v3.y);
            *reinterpret_cast<float4*>(xb + 4) = make_float4(v3.z, v3.w, v4.x, v4.y);
            *reinterpret_cast<float2*>(xb + 8) = make_float2(v4.z, v4.w);
        } else {
            *reinterpret_cast<float2*>(xb + 10) = make_float2(v2.z, v2.w);
            *reinterpret_cast<float4*>(xb + 12) = v3;
            *reinterpret_cast<float4*>(xb + 16) = v4;
        }
    }
    __syncthreads();

    // ---------------- Phase 1: warp-parallel prefix scan + dinv ----------------
    {
        const int lane = t & 31;
        const int w = t >> 5;                 // warps 0,1 item0 g0/g1; warps 4,5 item1
        if ((w & 2) == 0 && lane < 25) {
            const int p2 = w >> 2, g2 = w & 1;
            int c0 = s.it[p2].cnt[g2][2 * lane];
            int c1 = s.it[p2].cnt[g2][2 * lane + 1];
            s.it[p2].dinv[g2][2 * lane]     = rsqrtf((float)(c0 + 1));
            s.it[p2].dinv[g2][2 * lane + 1] = rsqrtf((float)(c1 + 1));
            int pair = c0 + c1;
            int incl = pair;
#pragma unroll
            for (int off = 1; off < 32; off <<= 1) {
                int v = __shfl_up_sync(0x1ffffffu, incl, off);
                if (lane >= off) incl += v;
            }
            int excl = incl - pair;
            s.it[p2].start[g2][2 * lane] = excl;
            s.it[p2].start[g2][2 * lane + 1] = excl + c0;
            s.it[p2].cnt[g2][2 * lane] = excl;          // cursor
            s.it[p2].cnt[g2][2 * lane + 1] = excl + c0; // cursor
            if (lane == 24) s.it[p2].start[g2][NN] = incl;
        }
    }
    __syncthreads();

    // ---------------- Phase 2: scatter edges sorted by dst (gmem re-read, L2-hot) ----------------
    for (int i = tt; i < 2 * E; i += 128) {
        int g = i / E, e = i - g * E;
        const int* adj = (g == 0 ? uadj : radj) + (size_t)item * 2 * E;
        int sr = adj[e], ds = adj[E + e];
        int pos = atomicAdd(&s.it[p].cnt[g][ds], 1);
        s.it[p].srcsorted[g][pos] = (unsigned short)sr;
    }
    __syncthreads();

    // ---------------- Phase 3: gather GCN + cross matvec + cosine + MLPs ----------------
    float h2a[20];
    const int g3 = (tt < 100) ? (tt / NN) : 0;
    const int n3 = (tt < 100) ? (tt - g3 * NN) : 0;
    if (tt < 100) {
        PerItem& pi = s.it[p];
        float dn = pi.dinv[g3][n3];
        float d2 = dn * dn;
        ull sva[5];
        {
            ull d2p = pk2(d2, d2);
            const ull* cb2 = reinterpret_cast<const ull*>(&s.convb[0]);
            const ull* cself = reinterpret_cast<const ull*>(&pi.u.cc.convp[g3][n3][0]);
#pragma unroll
            for (int q = 0; q < 5; q++) { sva[q] = cb2[q]; FMA2(sva[q], d2p, cself[q]); }
        }
        int e0 = pi.start[g3][n3], e1 = pi.start[g3][n3 + 1];
        for (int i = e0; i < e1; i++) {
            int sr = pi.srcsorted[g3][i];
            float norm = dn * pi.dinv[g3][sr];
            ull np = pk2(norm, norm);
            const ulonglong2* cr = reinterpret_cast<const ulonglong2*>(&pi.u.cc.convp[g3][sr][0]);
            ulonglong2 C0 = cr[0], C1 = cr[1];
            ull C4 = *reinterpret_cast<const ull*>(&pi.u.cc.convp[g3][sr][8]);
            FMA2(sva[0], np, C0.x); FMA2(sva[1], np, C0.y);
            FMA2(sva[2], np, C1.x); FMA2(sva[3], np, C1.y);
            FMA2(sva[4], np, C4);
        }
        float sv[10];
#pragma unroll
        for (int q = 0; q < 5; q++) {
            float2 f = unpk(sva[q]);
            sv[q * 2] = f.x; sv[q * 2 + 1] = f.y;
        }

        // cross matvec: cv = attn[n3,:] @ crossp[other] — pair-packed rows:
        // 5 LDS.128 serve TWO m-rows (2.5 loads/row instead of 3)
        ull cacc[5];
#pragma unroll
        for (int q = 0; q < 5; q++) cacc[q] = 0ull;
        const float* Arow = &s.attn[n3][0];
        const float* cbase = &pi.u.cc.crosspp[1 - g3][0][0];
#pragma unroll 5
        for (int q = 0; q < 25; q++) {
            float Av0 = Arow[2 * q], Av1 = Arow[2 * q + 1];
            ull a0 = pk2(Av0, Av0), a1 = pk2(Av1, Av1);
            const ulonglong2* cr = reinterpret_cast<const ulonglong2*>(cbase + q * 20);
            ulonglong2 P0 = cr[0], P1 = cr[1], P2 = cr[2], P3 = cr[3], P4 = cr[4];
            FMA2(cacc[0], a0, P0.x); FMA2(cacc[1], a0, P0.y);
            FMA2(cacc[2], a0, P1.x); FMA2(cacc[3], a0, P1.y);
            FMA2(cacc[4], a0, P2.x);
            FMA2(cacc[0], a1, P2.y); FMA2(cacc[1], a1, P3.x);
            FMA2(cacc[2], a1, P3.y); FMA2(cacc[3], a1, P4.x);
            FMA2(cacc[4], a1, P4.y);
        }
        float cv[10];
#pragma unroll
        for (int q = 0; q < 5; q++) {
            float2 f = unpk(cacc[q]);
            cv[q * 2] = f.x; cv[q * 2 + 1] = f.y;
        }

        // cosine with assign weighting — assign rows read as 5 LDS.64 (8B-aligned)
        float dot = 0.0f, na = 0.0f, nc = 0.0f;
        {
            const ull* asg = reinterpret_cast<const ull*>(&s.assign[n3][0]);
#pragma unroll
            for (int q = 0; q < 5; q++) {
                float2 aw = unpk(asg[q]);
                float av0 = aw.x * sv[q * 2],     cv0 = aw.x * cv[q * 2];
                float av1 = aw.y * sv[q * 2 + 1], cv1 = aw.y * cv[q * 2 + 1];
                dot += av0 * cv0 + av1 * cv1;
                na  += av0 * av0 + av1 * av1;
                nc  += cv0 * cv0 + cv1 * cv1;
            }
        }
        na = fmaxf(sqrtf(na), EPSV);
        nc = fmaxf(sqrtf(nc), EPSV);
        float dist = dot / (na * nc);

        // MLP layer 1 (packed)
        ull aa[10];
        {
            const ull* bb = reinterpret_cast<const ull*>(&s.mpb1[0]);
            const ull* w0 = reinterpret_cast<const ull*>(&s.mpw1p[0][0]);
            ull dd = pk2(dist, dist);
#pragma unroll
            for (int q = 0; q < 10; q++) { aa[q] = bb[q]; FMA2(aa[q], dd, w0[q]); }
#pragma unroll
            for (int k = 0; k < 10; k++) {
                ull xx = pk2(sv[k], sv[k]);
                const ulonglong2* wr = reinterpret_cast<const ulonglong2*>(&s.mpw1p[k + 1][0]);
                ulonglong2 W0 = wr[0], W1 = wr[1], W2 = wr[2], W3 = wr[3], W4 = wr[4];
                FMA2(aa[0], xx, W0.x); FMA2(aa[1], xx, W0.y);
                FMA2(aa[2], xx, W1.x); FMA2(aa[3], xx, W1.y);
                FMA2(aa[4], xx, W2.x); FMA2(aa[5], xx, W2.y);
                FMA2(aa[6], xx, W3.x); FMA2(aa[7], xx, W3.y);
                FMA2(aa[8], xx, W4.x); FMA2(aa[9], xx, W4.y);
            }
        }
        float h1f[20];
#pragma unroll
        for (int q = 0; q < 10; q++) {
            float2 f = unpk(aa[q]);
            h1f[q * 2] = fmaxf(f.x, 0.0f);
            h1f[q * 2 + 1] = fmaxf(f.y, 0.0f);
        }

        // MLP layer 2 (packed)
        ull hh[10];
        {
            const ull* bb = reinterpret_cast<const ull*>(&s.mpb2[0]);
#pragma unroll
            for (int q = 0; q < 10; q++) hh[q] = bb[q];
#pragma unroll
            for (int k = 0; k < 20; k++) {
                ull xx = pk2(h1f[k], h1f[k]);
                const ulonglong2* wr = reinterpret_cast<const ulonglong2*>(&s.mpw2p[k][0]);
                ulonglong2 W0 = wr[0], W1 = wr[1], W2 = wr[2], W3 = wr[3], W4 = wr[4];
                FMA2(hh[0], xx, W0.x); FMA2(hh[1], xx, W0.y);
                FMA2(hh[2], xx, W1.x); FMA2(hh[3], xx, W1.y);
                FMA2(hh[4], xx, W2.x); FMA2(hh[5], xx, W2.y);
                FMA2(hh[6], xx, W3.x); FMA2(hh[7], xx, W3.y);
                FMA2(hh[8], xx, W4.x); FMA2(hh[9], xx, W4.y);
            }
        }
#pragma unroll
        for (int q = 0; q < 10; q++) {
            float2 f = unpk(hh[q]);
            h2a[q * 2] = f.x; h2a[q * 2 + 1] = f.y;
        }
    }
    __syncthreads();   // convp/crosspp reads done before h2 overwrites union
    if (tt < 100) {
#pragma unroll
        for (int j = 0; j < 20; j++) s.it[p].u.h2[g3][n3][j] = h2a[j];
    }
    __syncthreads();

    // ---------------- Phase 4: node-max (3-way), features, FFN, sigmoid ----------------
    PerItem& pi = s.it[p];
    if (tt < 120) {
        int q = tt / 40, r = tt - q * 40;
        int g = r / 20, j = r - g * 20;
        int n0 = q * 17, n1 = (q == 2) ? NN : (q + 1) * 17;
        float m = -3.4e38f;
        for (int n = n0; n < n1; n++) m = fmaxf(m, pi.u.h2[g][n][j]);
        pi.pmax[q][g][j] = m;
    }
    __syncthreads();
    if (tt < 40) {
        int g = tt / 20, j = tt - g * 20;
        pi.gmax[g][j] = fmaxf(pi.pmax[0][g][j], fmaxf(pi.pmax[1][g][j], pi.pmax[2][g][j]));
    }
    __syncthreads();
    if (tt < 80) {
        int q = tt / 20, i = tt - q * 20;
        float gu = pi.gmax[0][i], gr = pi.gmax[1][i];
        pi.feat[tt] = (q == 0) ? gu : (q == 1) ? gr : (q == 2) ? gu * gr : fabsf(gu - gr);
    }
    __syncthreads();
    if (tt < 80) {
        int half = tt / 40, o = tt - half * 40;
        float acc2 = half ? 0.0f : fb1[o];
        for (int i = half * 40; i < half * 40 + 40; i++)
            acc2 += pi.feat[i] * fw1[i * 40 + o];
        pi.zz[half][o] = acc2;
    }
    __syncthreads();
    if (tt == 0) {
        float lg = fb2[0];
        for (int i = 0; i < 40; i++) {
            float z = fmaxf(pi.zz[0][i] + pi.zz[1][i], 0.0f);
            lg += z * fw2[i];
        }
        out[item] = 1.0f / (1.0f + expf(-lg));
    }
}

extern "C" void kernel_launch(void* const* d_in, const int* in_sizes, int n_in,
                              void* d_out, int out_size) {
    const int* utok   = (const int*)d_in[0];
    const int* rtok   = (const int*)d_in[1];
    const int* uadj   = (const int*)d_in[2];
    const int* radj   = (const int*)d_in[3];
    const float* emb  = (const float*)d_in[4];
    const float* cw   = (const float*)d_in[5];
    const float* cb   = (const float*)d_in[6];
    const float* xw   = (const float*)d_in[7];
    const float* attn = (const float*)d_in[8];
    const float* asw  = (const float*)d_in[9];
    const float* mw1  = (const float*)d_in[10];
    const float* mb1  = (const float*)d_in[11];
    const float* mw2  = (const float*)d_in[12];
    const float* mb2  = (const float*)d_in[13];
    const float* fw1  = (const float*)d_in[14];
    const float* fb1  = (const float*)d_in[15];
    const float* fw2  = (const float*)d_in[16];
    const float* fb2  = (const float*)d_in[17];
    float* out = (float*)d_out;

    int B = in_sizes[0] / NN;
    int E = in_sizes[2] / (2 * B);

    ptab_kernel<<<(VOCAB * 4 + 127) / 128, 128>>>(emb, cw, xw);

    cudaFuncSetAttribute(gmn_kernel, cudaFuncAttributeMaxDynamicSharedMemorySize,
                         (int)sizeof(Smem));
    gmn_kernel<<<B / IPB, TPB, sizeof(Smem)>>>(utok, rtok, uadj, radj,
                                               attn, asw, cb,
                                               mw1, mb1, mw2, mb2,
                                               fw1, fb1, fw2, fb2,
                                               out, E);
}

// round 15
// speedup vs baseline: 1.1219x; 1.1219x over previous
#include <cuda_runtime.h>

#define NN 50
#define TPB 256
#define IPB 2
#define EPSV 1e-8f
#define EMAXE 256
#define VOCAB 21128

typedef unsigned long long ull;

// Precomputed projected embedding table: row v = [emb[v]@conv_w (10) | emb[v]@cross_w (10)]
__device__ float g_ptab[VOCAB * 20];

// Warp-uniform weights in constant memory (LDCU path — off the L1/shared port)
__constant__ __align__(16) float c_mpw1[11][20];
__constant__ __align__(16) float c_mpw2[20][20];
__constant__ __align__(16) float c_mpb1[20];
__constant__ __align__(16) float c_mpb2[20];
__constant__ __align__(16) float c_convb[12];   // [10..11] stay zero-initialized

__device__ __forceinline__ ull pk2(float a, float b) {
    union { float2 f; ull u; } c;
    c.f = make_float2(a, b);
    return c.u;
}
__device__ __forceinline__ float2 unpk(ull u) {
    union { float2 f; ull u; } c;
    c.u = u;
    return c.f;
}
__device__ __forceinline__ float unpk_sum(ull u) {
    float2 f = unpk(u);
    return f.x + f.y;
}
#define FMA2(d, a, b) asm("fma.rn.f32x2 %0, %1, %2, %0;" : "+l"(d) : "l"(a), "l"(b))

// ---------------- Precompute: g_ptab = emb_table @ [conv_w | cross_w] ----------------
// v2 (measured best): 4 threads per vocab row; thread computes 5 outputs over all 128 dims.
__global__ void __launch_bounds__(128) ptab_kernel(
    const float* __restrict__ emb,
    const float* __restrict__ conv_w,
    const float* __restrict__ cross_w)
{
    __shared__ float wt[20][132];
    const int t = threadIdx.x;
    for (int i = t; i < 20 * 128; i += 128) {
        int j = i >> 7, d = i & 127;
        wt[j][d] = (j < 10) ? conv_w[d * 10 + j] : cross_w[d * 10 + (j - 10)];
    }
    __syncthreads();
    int idx = blockIdx.x * 128 + t;
    if (idx >= VOCAB * 4) return;
    int v = idx >> 2;
    int jq = idx & 3;          // j-quarter: outputs jq*5 .. jq*5+4

    ull acc[5];
#pragma unroll
    for (int q = 0; q < 5; q++) acc[q] = 0ull;
    const float4* ep = reinterpret_cast<const float4*>(emb + (size_t)v * 128);
    const float* wbase = &wt[jq * 5][0];
#pragma unroll 4
    for (int c4 = 0; c4 < 32; c4++) {
        float4 e = ep[c4];
        ull e01 = pk2(e.x, e.y), e23 = pk2(e.z, e.w);
#pragma unroll
        for (int q = 0; q < 5; q++) {
            float4 w = *reinterpret_cast<const float4*>(wbase + q * 132 + c4 * 4);
            FMA2(acc[q], e01, pk2(w.x, w.y));
            FMA2(acc[q], e23, pk2(w.z, w.w));
        }
    }
    float* op = g_ptab + (size_t)v * 20 + jq * 5;
#pragma unroll
    for (int q = 0; q < 5; q++) op[q] = unpk_sum(acc[q]);
}

// ---------------- Main kernel: 2 items per CTA ----------------
struct PerItem {
    union {
        struct {
            float convp[2][NN][12];      // 4800 B (12-stride, 16B-aligned rows)
            float crosspp[2][25][20];    // 4000 B — PAIR-PACKED: rows 2q,2q+1 contiguous
        } cc;
        float h2[2][NN][21];             // 8400 B
    } u;
    float dinv[2][NN];
    float gmax[2][20];
    float pmax[3][2][20];
    float feat[80];
    float zz[2][40];
    int   cnt[2][52];                  // histogram, then scatter cursor
    int   start[2][52];                // exclusive prefix (start[g][NN] = E)
    unsigned short srcsorted[2][EMAXE];
};

struct Smem {
    float attn[NN][51];                // shared constants (loaded once per CTA)
    float _p0[2];
    float assign[NN][10];
    PerItem it[IPB];
};

__global__ void __launch_bounds__(TPB, 4) gmn_kernel(
    const int* __restrict__ utok, const int* __restrict__ rtok,
    const int* __restrict__ uadj, const int* __restrict__ radj,
    const float* __restrict__ attn,
    const float* __restrict__ assignw,
    const float* __restrict__ fw1, const float* __restrict__ fb1,
    const float* __restrict__ fw2, const float* __restrict__ fb2,
    float* __restrict__ out, int E)
{
    extern __shared__ char smraw[];
    Smem& s = *reinterpret_cast<Smem*>(smraw);
    const int t = threadIdx.x;
    const int tt = t & 127;            // per-item thread id
    const int p = t >> 7;              // item slot 0/1
    const int item = blockIdx.x * IPB + p;

    // ---------------- Phase 0: shared constants (256 threads) + per-item init ----------------
    for (int i = t; i < NN * NN; i += TPB) s.attn[i / NN][i % NN] = attn[i];
    for (int i = t; i < NN * 10; i += TPB) s.assign[i / 10][i % 10] = assignw[i];
    if (tt < 104) reinterpret_cast<int*>(&s.it[p].cnt[0][0])[tt] = 0;
    __syncthreads();

    // ---------------- Phase 0b: histogram (gmem dst reads) + ptab gather ----------------
    for (int i = tt; i < 2 * E; i += 128) {
        int g = i / E, e = i - g * E;
        const int* adj = (g == 0 ? uadj : radj) + (size_t)item * 2 * E;
        atomicAdd(&s.it[p].cnt[g][adj[E + e]], 1);
    }
    if (tt < 100) {
        int g = tt / NN, r = tt - (tt / NN) * NN;
        int tokv = (g == 0 ? utok : rtok)[item * NN + r];
        const float4* tb = reinterpret_cast<const float4*>(g_ptab + (size_t)tokv * 20);
        float4 v0 = tb[0], v1 = tb[1], v2 = tb[2], v3 = tb[3], v4 = tb[4];
        float4* cp = reinterpret_cast<float4*>(&s.it[p].u.cc.convp[g][r][0]);
        cp[0] = v0;
        cp[1] = v1;
        cp[2] = make_float4(v2.x, v2.y, 0.f, 0.f);
        // cross projection into pair-packed layout: row r lives in pair r>>1, half r&1
        float* xb = &s.it[p].u.cc.crosspp[g][r >> 1][0];
        if ((r & 1) == 0) {
            *reinterpret_cast<float4*>(xb + 0) = make_float4(v2.z, v2.w, v3.x, v3.y);
            *reinterpret_cast<float4*>(xb + 4) = make_float4(v3.z, v3.w, v4.x, v4.y);
            *reinterpret_cast<float2*>(xb + 8) = make_float2(v4.z, v4.w);
        } else {
            *reinterpret_cast<float2*>(xb + 10) = make_float2(v2.z, v2.w);
            *reinterpret_cast<float4*>(xb + 12) = v3;
            *reinterpret_cast<float4*>(xb + 16) = v4;
        }
    }
    __syncthreads();

    // ---------------- Phase 1: warp-parallel prefix scan + dinv ----------------
    {
        const int lane = t & 31;
        const int w = t >> 5;                 // warps 0,1 item0 g0/g1; warps 4,5 item1
        if ((w & 2) == 0 && lane < 25) {
            const int p2 = w >> 2, g2 = w & 1;
            int c0 = s.it[p2].cnt[g2][2 * lane];
            int c1 = s.it[p2].cnt[g2][2 * lane + 1];
            s.it[p2].dinv[g2][2 * lane]     = rsqrtf((float)(c0 + 1));
            s.it[p2].dinv[g2][2 * lane + 1] = rsqrtf((float)(c1 + 1));
            int pair = c0 + c1;
            int incl = pair;
#pragma unroll
            for (int off = 1; off < 32; off <<= 1) {
                int v = __shfl_up_sync(0x1ffffffu, incl, off);
                if (lane >= off) incl += v;
            }
            int excl = incl - pair;
            s.it[p2].start[g2][2 * lane] = excl;
            s.it[p2].start[g2][2 * lane + 1] = excl + c0;
            s.it[p2].cnt[g2][2 * lane] = excl;          // cursor
            s.it[p2].cnt[g2][2 * lane + 1] = excl + c0; // cursor
            if (lane == 24) s.it[p2].start[g2][NN] = incl;
        }
    }
    __syncthreads();

    // ---------------- Phase 2: scatter edges sorted by dst (gmem re-read, L2-hot) ----------------
    for (int i = tt; i < 2 * E; i += 128) {
        int g = i / E, e = i - g * E;
        const int* adj = (g == 0 ? uadj : radj) + (size_t)item * 2 * E;
        int sr = adj[e], ds = adj[E + e];
        int pos = atomicAdd(&s.it[p].cnt[g][ds], 1);
        s.it[p].srcsorted[g][pos] = (unsigned short)sr;
    }
    __syncthreads();

    // ---------------- Phase 3: gather GCN + cross matvec + cosine + MLPs ----------------
    float h2a[20];
    const int g3 = (tt < 100) ? (tt / NN) : 0;
    const int n3 = (tt < 100) ? (tt - g3 * NN) : 0;
    if (tt < 100) {
        PerItem& pi = s.it[p];
        float dn = pi.dinv[g3][n3];
        float d2 = dn * dn;
        ull sva[5];
        {
            ull d2p = pk2(d2, d2);
            const ull* cb2 = reinterpret_cast<const ull*>(&c_convb[0]);
            const ull* cself = reinterpret_cast<const ull*>(&pi.u.cc.convp[g3][n3][0]);
#pragma unroll
            for (int q = 0; q < 5; q++) { sva[q] = cb2[q]; FMA2(sva[q], d2p, cself[q]); }
        }
        int e0 = pi.start[g3][n3], e1 = pi.start[g3][n3 + 1];
        for (int i = e0; i < e1; i++) {
            int sr = pi.srcsorted[g3][i];
            float norm = dn * pi.dinv[g3][sr];
            ull np = pk2(norm, norm);
            const ulonglong2* cr = reinterpret_cast<const ulonglong2*>(&pi.u.cc.convp[g3][sr][0]);
            ulonglong2 C0 = cr[0], C1 = cr[1];
            ull C4 = *reinterpret_cast<const ull*>(&pi.u.cc.convp[g3][sr][8]);
            FMA2(sva[0], np, C0.x); FMA2(sva[1], np, C0.y);
            FMA2(sva[2], np, C1.x); FMA2(sva[3], np, C1.y);
            FMA2(sva[4], np, C4);
        }
        float sv[10];
#pragma unroll
        for (int q = 0; q < 5; q++) {
            float2 f = unpk(sva[q]);
            sv[q * 2] = f.x; sv[q * 2 + 1] = f.y;
        }

        // cross matvec: cv = attn[n3,:] @ crossp[other] — pair-packed rows:
        // 5 LDS.128 serve TWO m-rows (2.5 loads/row instead of 3)
        ull cacc[5];
#pragma unroll
        for (int q = 0; q < 5; q++) cacc[q] = 0ull;
        const float* Arow = &s.attn[n3][0];
        const float* cbase = &pi.u.cc.crosspp[1 - g3][0][0];
#pragma unroll 5
        for (int q = 0; q < 25; q++) {
            float Av0 = Arow[2 * q], Av1 = Arow[2 * q + 1];
            ull a0 = pk2(Av0, Av0), a1 = pk2(Av1, Av1);
            const ulonglong2* cr = reinterpret_cast<const ulonglong2*>(cbase + q * 20);
            ulonglong2 P0 = cr[0], P1 = cr[1], P2 = cr[2], P3 = cr[3], P4 = cr[4];
            FMA2(cacc[0], a0, P0.x); FMA2(cacc[1], a0, P0.y);
            FMA2(cacc[2], a0, P1.x); FMA2(cacc[3], a0, P1.y);
            FMA2(cacc[4], a0, P2.x);
            FMA2(cacc[0], a1, P2.y); FMA2(cacc[1], a1, P3.x);
            FMA2(cacc[2], a1, P3.y); FMA2(cacc[3], a1, P4.x);
            FMA2(cacc[4], a1, P4.y);
        }
        float cv[10];
#pragma unroll
        for (int q = 0; q < 5; q++) {
            float2 f = unpk(cacc[q]);
            cv[q * 2] = f.x; cv[q * 2 + 1] = f.y;
        }

        // cosine with assign weighting (scalar assign reads — measured-best form)
        float dot = 0.0f, na = 0.0f, nc = 0.0f;
#pragma unroll
        for (int j = 0; j < 10; j++) {
            float aw = s.assign[n3][j];
            float av = aw * sv[j], cw2 = aw * cv[j];
            dot += av * cw2; na += av * av; nc += cw2 * cw2;
        }
        na = fmaxf(sqrtf(na), EPSV);
        nc = fmaxf(sqrtf(nc), EPSV);
        float dist = dot / (na * nc);

        // MLP layer 1 (weights from constant memory — uniform LDCU path)
        ull aa[10];
        {
            const ull* bb = reinterpret_cast<const ull*>(&c_mpb1[0]);
            const ull* w0 = reinterpret_cast<const ull*>(&c_mpw1[0][0]);
            ull dd = pk2(dist, dist);
#pragma unroll
            for (int q = 0; q < 10; q++) { aa[q] = bb[q]; FMA2(aa[q], dd, w0[q]); }
#pragma unroll
            for (int k = 0; k < 10; k++) {
                ull xx = pk2(sv[k], sv[k]);
                const ulonglong2* wr = reinterpret_cast<const ulonglong2*>(&c_mpw1[k + 1][0]);
                ulonglong2 W0 = wr[0], W1 = wr[1], W2 = wr[2], W3 = wr[3], W4 = wr[4];
                FMA2(aa[0], xx, W0.x); FMA2(aa[1], xx, W0.y);
                FMA2(aa[2], xx, W1.x); FMA2(aa[3], xx, W1.y);
                FMA2(aa[4], xx, W2.x); FMA2(aa[5], xx, W2.y);
                FMA2(aa[6], xx, W3.x); FMA2(aa[7], xx, W3.y);
                FMA2(aa[8], xx, W4.x); FMA2(aa[9], xx, W4.y);
            }
        }
        float h1f[20];
#pragma unroll
        for (int q = 0; q < 10; q++) {
            float2 f = unpk(aa[q]);
            h1f[q * 2] = fmaxf(f.x, 0.0f);
            h1f[q * 2 + 1] = fmaxf(f.y, 0.0f);
        }

        // MLP layer 2 (weights from constant memory)
        ull hh[10];
        {
            const ull* bb = reinterpret_cast<const ull*>(&c_mpb2[0]);
#pragma unroll
            for (int q = 0; q < 10; q++) hh[q] = bb[q];
#pragma unroll
            for (int k = 0; k < 20; k++) {
                ull xx = pk2(h1f[k], h1f[k]);
                const ulonglong2* wr = reinterpret_cast<const ulonglong2*>(&c_mpw2[k][0]);
                ulonglong2 W0 = wr[0], W1 = wr[1], W2 = wr[2], W3 = wr[3], W4 = wr[4];
                FMA2(hh[0], xx, W0.x); FMA2(hh[1], xx, W0.y);
                FMA2(hh[2], xx, W1.x); FMA2(hh[3], xx, W1.y);
                FMA2(hh[4], xx, W2.x); FMA2(hh[5], xx, W2.y);
                FMA2(hh[6], xx, W3.x); FMA2(hh[7], xx, W3.y);
                FMA2(hh[8], xx, W4.x); FMA2(hh[9], xx, W4.y);
            }
        }
#pragma unroll
        for (int q = 0; q < 10; q++) {
            float2 f = unpk(hh[q]);
            h2a[q * 2] = f.x; h2a[q * 2 + 1] = f.y;
        }
    }
    __syncthreads();   // convp/crosspp reads done before h2 overwrites union
    if (tt < 100) {
#pragma unroll
        for (int j = 0; j < 20; j++) s.it[p].u.h2[g3][n3][j] = h2a[j];
    }
    __syncthreads();

    // ---------------- Phase 4: node-max (3-way), features, FFN, sigmoid ----------------
    PerItem& pi = s.it[p];
    if (tt < 120) {
        int q = tt / 40, r = tt - q * 40;
        int g = r / 20, j = r - g * 20;
        int n0 = q * 17, n1 = (q == 2) ? NN : (q + 1) * 17;
        float m = -3.4e38f;
        for (int n = n0; n < n1; n++) m = fmaxf(m, pi.u.h2[g][n][j]);
        pi.pmax[q][g][j] = m;
    }
    __syncthreads();
    if (tt < 40) {
        int g = tt / 20, j = tt - g * 20;
        pi.gmax[g][j] = fmaxf(pi.pmax[0][g][j], fmaxf(pi.pmax[1][g][j], pi.pmax[2][g][j]));
    }
    __syncthreads();
    if (tt < 80) {
        int q = tt / 20, i = tt - q * 20;
        float gu = pi.gmax[0][i], gr = pi.gmax[1][i];
        pi.feat[tt] = (q == 0) ? gu : (q == 1) ? gr : (q == 2) ? gu * gr : fabsf(gu - gr);
    }
    __syncthreads();
    if (tt < 80) {
        int half = tt / 40, o = tt - half * 40;
        float acc2 = half ? 0.0f : fb1[o];
        for (int i = half * 40; i < half * 40 + 40; i++)
            acc2 += pi.feat[i] * fw1[i * 40 + o];
        pi.zz[half][o] = acc2;
    }
    __syncthreads();
    if (tt == 0) {
        float lg = fb2[0];
        for (int i = 0; i < 40; i++) {
            float z = fmaxf(pi.zz[0][i] + pi.zz[1][i], 0.0f);
            lg += z * fw2[i];
        }
        out[item] = 1.0f / (1.0f + expf(-lg));
    }
}

extern "C" void kernel_launch(void* const* d_in, const int* in_sizes, int n_in,
                              void* d_out, int out_size) {
    const int* utok   = (const int*)d_in[0];
    const int* rtok   = (const int*)d_in[1];
    const int* uadj   = (const int*)d_in[2];
    const int* radj   = (const int*)d_in[3];
    const float* emb  = (const float*)d_in[4];
    const float* cw   = (const float*)d_in[5];
    const float* cb   = (const float*)d_in[6];
    const float* xw   = (const float*)d_in[7];
    const float* attn = (const float*)d_in[8];
    const float* asw  = (const float*)d_in[9];
    const float* mw1  = (const float*)d_in[10];
    const float* mb1  = (const float*)d_in[11];
    const float* mw2  = (const float*)d_in[12];
    const float* mb2  = (const float*)d_in[13];
    const float* fw1  = (const float*)d_in[14];
    const float* fb1  = (const float*)d_in[15];
    const float* fw2  = (const float*)d_in[16];
    const float* fb2  = (const float*)d_in[17];
    float* out = (float*)d_out;

    int B = in_sizes[0] / NN;
    int E = in_sizes[2] / (2 * B);

    // Populate constant-memory weights (async D2D copies — graph-capturable)
    cudaMemcpyToSymbolAsync(c_mpw1, mw1, 11 * 20 * sizeof(float), 0, cudaMemcpyDeviceToDevice);
    cudaMemcpyToSymbolAsync(c_mpw2, mw2, 20 * 20 * sizeof(float), 0, cudaMemcpyDeviceToDevice);
    cudaMemcpyToSymbolAsync(c_mpb1, mb1, 20 * sizeof(float), 0, cudaMemcpyDeviceToDevice);
    cudaMemcpyToSymbolAsync(c_mpb2, mb2, 20 * sizeof(float), 0, cudaMemcpyDeviceToDevice);
    cudaMemcpyToSymbolAsync(c_convb, cb, 10 * sizeof(float), 0, cudaMemcpyDeviceToDevice);

    ptab_kernel<<<(VOCAB * 4 + 127) / 128, 128>>>(emb, cw, xw);

    cudaFuncSetAttribute(gmn_kernel, cudaFuncAttributeMaxDynamicSharedMemorySize,
                         (int)sizeof(Smem));
    gmn_kernel<<<B / IPB, TPB, sizeof(Smem)>>>(utok, rtok, uadj, radj,
                                               attn, asw,
                                               fw1, fb1, fw2, fb2,
                                               out, E);
}

// round 17
// speedup vs baseline: 1.1784x; 1.0504x over previous
#include <cuda_runtime.h>

#define NN 50
#define TPB 256
#define IPB 2
#define EPSV 1e-8f
#define EMAXE 256
#define VOCAB 21128

typedef unsigned long long ull;

// Precomputed projected embedding table: row v = [emb[v]@conv_w (10) | emb[v]@cross_w (10)]
__device__ float g_ptab[VOCAB * 20];

// All warp-uniform weights in ONE constant struct (single symbol -> single copy node)
struct __align__(16) ConstW {
    float mpw1[11][20];   // offset 0 B    (rows 80 B, 16B-aligned)
    float mpw2[20][20];   // offset 880 B
    float mpb1[20];       // offset 2480 B
    float mpb2[20];       // offset 2560 B
    float convb[12];      // offset 2640 B (10 valid + 2 zero)
};
__constant__ ConstW c_w;
__device__ __align__(16) float g_stage[672];   // staging buffer, same layout

__device__ __forceinline__ ull pk2(float a, float b) {
    union { float2 f; ull u; } c;
    c.f = make_float2(a, b);
    return c.u;
}
__device__ __forceinline__ float2 unpk(ull u) {
    union { float2 f; ull u; } c;
    c.u = u;
    return c.f;
}
__device__ __forceinline__ float unpk_sum(ull u) {
    float2 f = unpk(u);
    return f.x + f.y;
}
#define FMA2(d, a, b) asm("fma.rn.f32x2 %0, %1, %2, %0;" : "+l"(d) : "l"(a), "l"(b))

// ---------------- Stage kernel: pack 5 weight arrays into g_stage (ConstW layout) ----------------
__global__ void __launch_bounds__(256) stage_kernel(
    const float* __restrict__ mw1, const float* __restrict__ mw2,
    const float* __restrict__ mb1, const float* __restrict__ mb2,
    const float* __restrict__ cb)
{
    int i = threadIdx.x + blockIdx.x * 256;
    if (i >= 672) return;
    float v;
    if (i < 220)      v = mw1[i];
    else if (i < 620) v = mw2[i - 220];
    else if (i < 640) v = mb1[i - 620];
    else if (i < 660) v = mb2[i - 640];
    else              v = (i - 660 < 10) ? cb[i - 660] : 0.0f;
    g_stage[i] = v;
}

// ---------------- Precompute: g_ptab = emb_table @ [conv_w | cross_w] ----------------
// v2 (measured best): 4 threads per vocab row; thread computes 5 outputs over all 128 dims.
__global__ void __launch_bounds__(128) ptab_kernel(
    const float* __restrict__ emb,
    const float* __restrict__ conv_w,
    const float* __restrict__ cross_w)
{
    __shared__ float wt[20][132];
    const int t = threadIdx.x;
    for (int i = t; i < 20 * 128; i += 128) {
        int j = i >> 7, d = i & 127;
        wt[j][d] = (j < 10) ? conv_w[d * 10 + j] : cross_w[d * 10 + (j - 10)];
    }
    __syncthreads();
    int idx = blockIdx.x * 128 + t;
    if (idx >= VOCAB * 4) return;
    int v = idx >> 2;
    int jq = idx & 3;          // j-quarter: outputs jq*5 .. jq*5+4

    ull acc[5];
#pragma unroll
    for (int q = 0; q < 5; q++) acc[q] = 0ull;
    const float4* ep = reinterpret_cast<const float4*>(emb + (size_t)v * 128);
    const float* wbase = &wt[jq * 5][0];
#pragma unroll 4
    for (int c4 = 0; c4 < 32; c4++) {
        float4 e = ep[c4];
        ull e01 = pk2(e.x, e.y), e23 = pk2(e.z, e.w);
#pragma unroll
        for (int q = 0; q < 5; q++) {
            float4 w = *reinterpret_cast<const float4*>(wbase + q * 132 + c4 * 4);
            FMA2(acc[q], e01, pk2(w.x, w.y));
            FMA2(acc[q], e23, pk2(w.z, w.w));
        }
    }
    float* op = g_ptab + (size_t)v * 20 + jq * 5;
#pragma unroll
    for (int q = 0; q < 5; q++) op[q] = unpk_sum(acc[q]);
}

// ---------------- Main kernel: 2 items per CTA ----------------
struct PerItem {
    union {
        struct {
            float convp[2][NN][12];      // 4800 B (12-stride, 16B-aligned rows)
            float crosspp[2][25][20];    // 4000 B — PAIR-PACKED: rows 2q,2q+1 contiguous
        } cc;
        float h2[2][NN][21];             // 8400 B
    } u;
    float dinv[2][NN];
    float gmax[2][20];
    float pmax[3][2][20];
    float feat[80];
    float zz[2][40];
    int   cnt[2][52];                  // histogram, then scatter cursor
    int   start[2][52];                // exclusive prefix (start[g][NN] = E)
    unsigned short srcsorted[2][EMAXE];
};

struct Smem {
    float attn[NN][51];                // shared constants (loaded once per CTA)
    float _p0[2];
    float assign[NN][10];
    PerItem it[IPB];
};

__global__ void __launch_bounds__(TPB, 4) gmn_kernel(
    const int* __restrict__ utok, const int* __restrict__ rtok,
    const int* __restrict__ uadj, const int* __restrict__ radj,
    const float* __restrict__ attn,
    const float* __restrict__ assignw,
    const float* __restrict__ fw1, const float* __restrict__ fb1,
    const float* __restrict__ fw2, const float* __restrict__ fb2,
    float* __restrict__ out, int E)
{
    extern __shared__ char smraw[];
    Smem& s = *reinterpret_cast<Smem*>(smraw);
    const int t = threadIdx.x;
    const int tt = t & 127;            // per-item thread id
    const int p = t >> 7;              // item slot 0/1
    const int item = blockIdx.x * IPB + p;

    // ---------------- Phase 0: shared constants (256 threads) + per-item init ----------------
    for (int i = t; i < NN * NN; i += TPB) s.attn[i / NN][i % NN] = attn[i];
    for (int i = t; i < NN * 10; i += TPB) s.assign[i / 10][i % 10] = assignw[i];
    if (tt < 104) reinterpret_cast<int*>(&s.it[p].cnt[0][0])[tt] = 0;
    __syncthreads();

    // ---------------- Phase 0b: histogram (gmem dst reads) + ptab gather ----------------
    for (int i = tt; i < 2 * E; i += 128) {
        int g = i / E, e = i - g * E;
        const int* adj = (g == 0 ? uadj : radj) + (size_t)item * 2 * E;
        atomicAdd(&s.it[p].cnt[g][adj[E + e]], 1);
    }
    if (tt < 100) {
        int g = tt / NN, r = tt - (tt / NN) * NN;
        int tokv = (g == 0 ? utok : rtok)[item * NN + r];
        const float4* tb = reinterpret_cast<const float4*>(g_ptab + (size_t)tokv * 20);
        float4 v0 = tb[0], v1 = tb[1], v2 = tb[2], v3 = tb[3], v4 = tb[4];
        float4* cp = reinterpret_cast<float4*>(&s.it[p].u.cc.convp[g][r][0]);
        cp[0] = v0;
        cp[1] = v1;
        cp[2] = make_float4(v2.x, v2.y, 0.f, 0.f);
        // cross projection into pair-packed layout: row r lives in pair r>>1, half r&1
        float* xb = &s.it[p].u.cc.crosspp[g][r >> 1][0];
        if ((r & 1) == 0) {
            *reinterpret_cast<float4*>(xb + 0) = make_float4(v2.z, v2.w, v3.x, v3.y);
            *reinterpret_cast<float4*>(xb + 4) = make_float4(v3.z, v3.w, v4.x, v4.y);
            *reinterpret_cast<float2*>(xb + 8) = make_float2(v4.z, v4.w);
        } else {
            *reinterpret_cast<float2*>(xb + 10) = make_float2(v2.z, v2.w);
            *reinterpret_cast<float4*>(xb + 12) = v3;
            *reinterpret_cast<float4*>(xb + 16) = v4;
        }
    }
    __syncthreads();

    // ---------------- Phase 1: warp-parallel prefix scan + dinv ----------------
    {
        const int lane = t & 31;
        const int w = t >> 5;                 // warps 0,1 item0 g0/g1; warps 4,5 item1
        if ((w & 2) == 0 && lane < 25) {
            const int p2 = w >> 2, g2 = w & 1;
            int c0 = s.it[p2].cnt[g2][2 * lane];
            int c1 = s.it[p2].cnt[g2][2 * lane + 1];
            s.it[p2].dinv[g2][2 * lane]     = rsqrtf((float)(c0 + 1));
            s.it[p2].dinv[g2][2 * lane + 1] = rsqrtf((float)(c1 + 1));
            int pair = c0 + c1;
            int incl = pair;
#pragma unroll
            for (int off = 1; off < 32; off <<= 1) {
                int v = __shfl_up_sync(0x1ffffffu, incl, off);
                if (lane >= off) incl += v;
            }
            int excl = incl - pair;
            s.it[p2].start[g2][2 * lane] = excl;
            s.it[p2].start[g2][2 * lane + 1] = excl + c0;
            s.it[p2].cnt[g2][2 * lane] = excl;          // cursor
            s.it[p2].cnt[g2][2 * lane + 1] = excl + c0; // cursor
            if (lane == 24) s.it[p2].start[g2][NN] = incl;
        }
    }
    __syncthreads();

    // ---------------- Phase 2: scatter edges sorted by dst (gmem re-read, L2-hot) ----------------
    for (int i = tt; i < 2 * E; i += 128) {
        int g = i / E, e = i - g * E;
        const int* adj = (g == 0 ? uadj : radj) + (size_t)item * 2 * E;
        int sr = adj[e], ds = adj[E + e];
        int pos = atomicAdd(&s.it[p].cnt[g][ds], 1);
        s.it[p].srcsorted[g][pos] = (unsigned short)sr;
    }
    __syncthreads();

    // ---------------- Phase 3: gather GCN + cross matvec + cosine + MLPs ----------------
    float h2a[20];
    const int g3 = (tt < 100) ? (tt / NN) : 0;
    const int n3 = (tt < 100) ? (tt - g3 * NN) : 0;
    if (tt < 100) {
        PerItem& pi = s.it[p];
        float dn = pi.dinv[g3][n3];
        float d2 = dn * dn;
        ull sva[5];
        {
            ull d2p = pk2(d2, d2);
            const ull* cb2 = reinterpret_cast<const ull*>(&c_w.convb[0]);
            const ull* cself = reinterpret_cast<const ull*>(&pi.u.cc.convp[g3][n3][0]);
#pragma unroll
            for (int q = 0; q < 5; q++) { sva[q] = cb2[q]; FMA2(sva[q], d2p, cself[q]); }
        }
        int e0 = pi.start[g3][n3], e1 = pi.start[g3][n3 + 1];
        for (int i = e0; i < e1; i++) {
            int sr = pi.srcsorted[g3][i];
            float norm = dn * pi.dinv[g3][sr];
            ull np = pk2(norm, norm);
            const ulonglong2* cr = reinterpret_cast<const ulonglong2*>(&pi.u.cc.convp[g3][sr][0]);
            ulonglong2 C0 = cr[0], C1 = cr[1];
            ull C4 = *reinterpret_cast<const ull*>(&pi.u.cc.convp[g3][sr][8]);
            FMA2(sva[0], np, C0.x); FMA2(sva[1], np, C0.y);
            FMA2(sva[2], np, C1.x); FMA2(sva[3], np, C1.y);
            FMA2(sva[4], np, C4);
        }
        float sv[10];
#pragma unroll
        for (int q = 0; q < 5; q++) {
            float2 f = unpk(sva[q]);
            sv[q * 2] = f.x; sv[q * 2 + 1] = f.y;
        }

        // cross matvec: cv = attn[n3,:] @ crossp[other] — pair-packed rows:
        // 5 LDS.128 serve TWO m-rows (2.5 loads/row instead of 3)
        ull cacc[5];
#pragma unroll
        for (int q = 0; q < 5; q++) cacc[q] = 0ull;
        const float* Arow = &s.attn[n3][0];
        const float* cbase = &pi.u.cc.crosspp[1 - g3][0][0];
#pragma unroll 5
        for (int q = 0; q < 25; q++) {
            float Av0 = Arow[2 * q], Av1 = Arow[2 * q + 1];
            ull a0 = pk2(Av0, Av0), a1 = pk2(Av1, Av1);
            const ulonglong2* cr = reinterpret_cast<const ulonglong2*>(cbase + q * 20);
            ulonglong2 P0 = cr[0], P1 = cr[1], P2 = cr[2], P3 = cr[3], P4 = cr[4];
            FMA2(cacc[0], a0, P0.x); FMA2(cacc[1], a0, P0.y);
            FMA2(cacc[2], a0, P1.x); FMA2(cacc[3], a0, P1.y);
            FMA2(cacc[4], a0, P2.x);
            FMA2(cacc[0], a1, P2.y); FMA2(cacc[1], a1, P3.x);
            FMA2(cacc[2], a1, P3.y); FMA2(cacc[3], a1, P4.x);
            FMA2(cacc[4], a1, P4.y);
        }
        float cv[10];
#pragma unroll
        for (int q = 0; q < 5; q++) {
            float2 f = unpk(cacc[q]);
            cv[q * 2] = f.x; cv[q * 2 + 1] = f.y;
        }

        // cosine with assign weighting (scalar assign reads — measured-best form)
        float dot = 0.0f, na = 0.0f, nc = 0.0f;
#pragma unroll
        for (int j = 0; j < 10; j++) {
            float aw = s.assign[n3][j];
            float av = aw * sv[j], cw2 = aw * cv[j];
            dot += av * cw2; na += av * av; nc += cw2 * cw2;
        }
        na = fmaxf(sqrtf(na), EPSV);
        nc = fmaxf(sqrtf(nc), EPSV);
        float dist = dot / (na * nc);

        // MLP layer 1 (weights from constant memory — uniform LDCU path)
        ull aa[10];
        {
            const ull* bb = reinterpret_cast<const ull*>(&c_w.mpb1[0]);
            const ull* w0 = reinterpret_cast<const ull*>(&c_w.mpw1[0][0]);
            ull dd = pk2(dist, dist);
#pragma unroll
            for (int q = 0; q < 10; q++) { aa[q] = bb[q]; FMA2(aa[q], dd, w0[q]); }
#pragma unroll
            for (int k = 0; k < 10; k++) {
                ull xx = pk2(sv[k], sv[k]);
                const ulonglong2* wr = reinterpret_cast<const ulonglong2*>(&c_w.mpw1[k + 1][0]);
                ulonglong2 W0 = wr[0], W1 = wr[1], W2 = wr[2], W3 = wr[3], W4 = wr[4];
                FMA2(aa[0], xx, W0.x); FMA2(aa[1], xx, W0.y);
                FMA2(aa[2], xx, W1.x); FMA2(aa[3], xx, W1.y);
                FMA2(aa[4], xx, W2.x); FMA2(aa[5], xx, W2.y);
                FMA2(aa[6], xx, W3.x); FMA2(aa[7], xx, W3.y);
                FMA2(aa[8], xx, W4.x); FMA2(aa[9], xx, W4.y);
            }
        }
        float h1f[20];
#pragma unroll
        for (int q = 0; q < 10; q++) {
            float2 f = unpk(aa[q]);
            h1f[q * 2] = fmaxf(f.x, 0.0f);
            h1f[q * 2 + 1] = fmaxf(f.y, 0.0f);
        }

        // MLP layer 2 (weights from constant memory)
        ull hh[10];
        {
            const ull* bb = reinterpret_cast<const ull*>(&c_w.mpb2[0]);
#pragma unroll
            for (int q = 0; q < 10; q++) hh[q] = bb[q];
#pragma unroll
            for (int k = 0; k < 20; k++) {
                ull xx = pk2(h1f[k], h1f[k]);
                const ulonglong2* wr = reinterpret_cast<const ulonglong2*>(&c_w.mpw2[k][0]);
                ulonglong2 W0 = wr[0], W1 = wr[1], W2 = wr[2], W3 = wr[3], W4 = wr[4];
                FMA2(hh[0], xx, W0.x); FMA2(hh[1], xx, W0.y);
                FMA2(hh[2], xx, W1.x); FMA2(hh[3], xx, W1.y);
                FMA2(hh[4], xx, W2.x); FMA2(hh[5], xx, W2.y);
                FMA2(hh[6], xx, W3.x); FMA2(hh[7], xx, W3.y);
                FMA2(hh[8], xx, W4.x); FMA2(hh[9], xx, W4.y);
            }
        }
#pragma unroll
        for (int q = 0; q < 10; q++) {
            float2 f = unpk(hh[q]);
            h2a[q * 2] = f.x; h2a[q * 2 + 1] = f.y;
        }
    }
    __syncthreads();   // convp/crosspp reads done before h2 overwrites union
    if (tt < 100) {
#pragma unroll
        for (int j = 0; j < 20; j++) s.it[p].u.h2[g3][n3][j] = h2a[j];
    }
    __syncthreads();

    // ---------------- Phase 4: node-max (3-way), features, FFN, sigmoid ----------------
    PerItem& pi = s.it[p];
    if (tt < 120) {
        int q = tt / 40, r = tt - q * 40;
        int g = r / 20, j = r - g * 20;
        int n0 = q * 17, n1 = (q == 2) ? NN : (q + 1) * 17;
        float m = -3.4e38f;
        for (int n = n0; n < n1; n++) m = fmaxf(m, pi.u.h2[g][n][j]);
        pi.pmax[q][g][j] = m;
    }
    __syncthreads();
    if (tt < 40) {
        int g = tt / 20, j = tt - g * 20;
        pi.gmax[g][j] = fmaxf(pi.pmax[0][g][j], fmaxf(pi.pmax[1][g][j], pi.pmax[2][g][j]));
    }
    __syncthreads();
    if (tt < 80) {
        int q = tt / 20, i = tt - q * 20;
        float gu = pi.gmax[0][i], gr = pi.gmax[1][i];
        pi.feat[tt] = (q == 0) ? gu : (q == 1) ? gr : (q == 2) ? gu * gr : fabsf(gu - gr);
    }
    __syncthreads();
    if (tt < 80) {
        int half = tt / 40, o = tt - half * 40;
        float acc2 = half ? 0.0f : fb1[o];
        for (int i = half * 40; i < half * 40 + 40; i++)
            acc2 += pi.feat[i] * fw1[i * 40 + o];
        pi.zz[half][o] = acc2;
    }
    __syncthreads();
    if (tt == 0) {
        float lg = fb2[0];
        for (int i = 0; i < 40; i++) {
            float z = fmaxf(pi.zz[0][i] + pi.zz[1][i], 0.0f);
            lg += z * fw2[i];
        }
        out[item] = 1.0f / (1.0f + expf(-lg));
    }
}

extern "C" void kernel_launch(void* const* d_in, const int* in_sizes, int n_in,
                              void* d_out, int out_size) {
    const int* utok   = (const int*)d_in[0];
    const int* rtok   = (const int*)d_in[1];
    const int* uadj   = (const int*)d_in[2];
    const int* radj   = (const int*)d_in[3];
    const float* emb  = (const float*)d_in[4];
    const float* cw   = (const float*)d_in[5];
    const float* cb   = (const float*)d_in[6];
    const float* xw   = (const float*)d_in[7];
    const float* attn = (const float*)d_in[8];
    const float* asw  = (const float*)d_in[9];
    const float* mw1  = (const float*)d_in[10];
    const float* mb1  = (const float*)d_in[11];
    const float* mw2  = (const float*)d_in[12];
    const float* mb2  = (const float*)d_in[13];
    const float* fw1  = (const float*)d_in[14];
    const float* fb1  = (const float*)d_in[15];
    const float* fw2  = (const float*)d_in[16];
    const float* fb2  = (const float*)d_in[17];
    float* out = (float*)d_out;

    int B = in_sizes[0] / NN;
    int E = in_sizes[2] / (2 * B);

    // Pack all weights into staging buffer, then ONE constant-memory copy.
    // FIX vs round 16: resolve the DEVICE address of g_stage (the raw symbol is
    // the host shadow and is not a valid D2D source pointer).
    stage_kernel<<<3, 256>>>(mw1, mw2, mb1, mb2, cb);
    void* stage_dev = nullptr;
    cudaGetSymbolAddress(&stage_dev, g_stage);
    cudaMemcpyToSymbolAsync(c_w, stage_dev, sizeof(ConstW), 0, cudaMemcpyDeviceToDevice);

    ptab_kernel<<<(VOCAB * 4 + 127) / 128, 128>>>(emb, cw, xw);

    cudaFuncSetAttribute(gmn_kernel, cudaFuncAttributeMaxDynamicSharedMemorySize,
                         (int)sizeof(Smem));
    gmn_kernel<<<B / IPB, TPB, sizeof(Smem)>>>(utok, rtok, uadj, radj,
                                               attn, asw,
                                               fw1, fb1, fw2, fb2,
                                               out, E);
}